// round 4
// baseline (speedup 1.0000x reference)
#include <cuda_runtime.h>
#include <cstdint>

#define BB 2
#define NN 8192
#define CC 80
#define NW 128   /* 64-box chunks */
#define KCAP 128 /* max suppressors recorded per box */

typedef unsigned long long u64;
typedef unsigned int u32;

/* output layout (concatenated flat float32, tuple order) */
#define OFF_BOXES 0
#define OFF_MS    (BB*NN*4)
#define OFF_LB    (OFF_MS + BB*NN)
#define OFF_KEEP  (OFF_LB + BB*NN)
#define OFF_ALL   (OFF_KEEP + BB*NN)

/* static device scratch */
__device__ u64 g_diagT[BB][NW][64];    /* transposed in-chunk 64x64 tiles */
__device__ u64 g_keys[BB][NN];
__device__ u32 g_sorted[BB][NN];
__device__ int g_valid[BB][NN];
__device__ int g_cnt[BB][NN];          /* suppressor counts (sorted coords) */
__device__ u32 g_list[BB][NN][KCAP];   /* suppressor lists  (sorted coords) */

/* ------------------------------------------------------------------ */
/* Kernel 1: sigmoid / max / argmax / box decode / valid / sort keys   */
__global__ void prep_kernel(const float* __restrict__ logits,
                            const float* __restrict__ deltas,
                            const float* __restrict__ anchors,
                            float* __restrict__ out)
{
    int wid  = (blockIdx.x * blockDim.x + threadIdx.x) >> 5;
    int lane = threadIdx.x & 31;
    if (wid >= BB * NN) return;
    int b = wid / NN, n = wid % NN;

    const float* lg = logits + (size_t)wid * CC;
    float* as_out   = out + OFF_ALL + (size_t)wid * CC;

    float v0 = lg[lane];
    float v1 = lg[lane + 32];
    float v2 = (lane < 16) ? lg[lane + 64] : -INFINITY;

    as_out[lane]      = 1.0f / (1.0f + expf(-v0));
    as_out[lane + 32] = 1.0f / (1.0f + expf(-v1));
    if (lane < 16) as_out[lane + 64] = 1.0f / (1.0f + expf(-v2));

    float mv = v0; int mi = lane;
    if (v1 > mv) { mv = v1; mi = lane + 32; }
    if (v2 > mv) { mv = v2; mi = lane + 64; }

    for (int off = 16; off; off >>= 1) {
        float ov = __shfl_down_sync(0xffffffffu, mv, off);
        int   oi = __shfl_down_sync(0xffffffffu, mi, off);
        if (ov > mv || (ov == mv && oi < mi)) { mv = ov; mi = oi; }
    }

    if (lane == 1) g_cnt[b][n] = 0;   /* zero suppressor counters */

    if (lane == 0) {
        float ms = 1.0f / (1.0f + expf(-mv));
        out[OFF_MS + wid] = ms;
        out[OFF_LB + wid] = (float)mi;

        const float* dl = deltas  + (size_t)wid * 4;
        const float* an = anchors + (size_t)n * 4;
        float a0 = an[0], a1 = an[1], a2 = an[2], a3 = an[3];
        float aw = a2 - a0, ah = a3 - a1;
        float acx = a0 + 0.5f * aw, acy = a1 + 0.5f * ah;
        float dx = dl[0], dy = dl[1];
        float dw = fminf(dl[2], 4.0f), dh = fminf(dl[3], 4.0f);
        float pcx = dx * aw + acx, pcy = dy * ah + acy;
        float pw = expf(dw) * aw, ph = expf(dh) * ah;
        float x1 = fminf(fmaxf(pcx - 0.5f * pw, 0.0f), 1.0f);
        float y1 = fminf(fmaxf(pcy - 0.5f * ph, 0.0f), 1.0f);
        float x2 = fminf(fmaxf(pcx + 0.5f * pw, 0.0f), 1.0f);
        float y2 = fminf(fmaxf(pcy + 0.5f * ph, 0.0f), 1.0f);

        float* bo = out + OFF_BOXES + (size_t)wid * 4;
        bo[0] = x1; bo[1] = y1; bo[2] = x2; bo[3] = y2;

        float w = x2 - x1, h = y2 - y1;
        int valid = (ms > 0.5f) && (w > 0.01f) && (h > 0.01f) &&
                    (w < 0.99f) && (h < 0.99f);
        g_valid[b][n] = valid;

        u32 ksb = ~__float_as_uint(ms);
        g_keys[b][n] = ((u64)ksb << 32) | (u32)n;
    }
}

/* ------------------------------------------------------------------ */
/* Kernel 2: bitonic sort of 8192 packed keys per batch                */
extern __shared__ u64 s_keys[];
__global__ void sort_kernel()
{
    int b = blockIdx.x;
    for (int i = threadIdx.x; i < NN; i += blockDim.x)
        s_keys[i] = g_keys[b][i];
    __syncthreads();

    for (int k = 2; k <= NN; k <<= 1) {
        for (int j = k >> 1; j > 0; j >>= 1) {
            for (int i = threadIdx.x; i < NN; i += blockDim.x) {
                int ixj = i ^ j;
                if (ixj > i) {
                    u64 a = s_keys[i];
                    u64 c = s_keys[ixj];
                    bool up = ((i & k) == 0);
                    if (up ? (a > c) : (a < c)) { s_keys[i] = c; s_keys[ixj] = a; }
                }
            }
            __syncthreads();
        }
    }
    for (int i = threadIdx.x; i < NN; i += blockDim.x)
        g_sorted[b][i] = (u32)(s_keys[i] & 0xffffffffull);
}

/* ------------------------------------------------------------------ */
/* Kernel 3: sparse suppressor pairs.                                  */
/* Tile (rb, cb) rb <= cb. rb rows = EARLIER sorted boxes, cb cols =   */
/* LATER boxes. Off-diag: append earlier row r to list[col c] when     */
/* IoU > thr. Diagonal: emit transposed 64x64 in-chunk tile.           */
__global__ void pairs_kernel(const float* __restrict__ out)
{
    int b = blockIdx.y;
    int L = blockIdx.x;
    int cb = (int)((sqrtf(8.0f * (float)L + 1.0f) - 1.0f) * 0.5f);
    while ((cb + 1) * (cb + 2) / 2 <= L) cb++;
    while (cb * (cb + 1) / 2 > L) cb--;
    int rb = L - cb * (cb + 1) / 2;     /* rb <= cb */

    int t = threadIdx.x;  /* 64 threads: one per ROW box */

    __shared__ float sx1[64], sy1[64], sx2[64], sy2[64], sar[64];
    __shared__ u64 srow[64];

    int cj = cb * 64 + t;
    u32 jidx = g_sorted[b][cj];
    float4 cbx = *(const float4*)(out + OFF_BOXES + ((size_t)b * NN + jidx) * 4);
    sx1[t] = cbx.x; sy1[t] = cbx.y; sx2[t] = cbx.z; sy2[t] = cbx.w;
    sar[t] = (cbx.z - cbx.x) * (cbx.w - cbx.y);
    __syncthreads();

    int i = rb * 64 + t;
    u32 iidx = g_sorted[b][i];
    float4 rbx = *(const float4*)(out + OFF_BOXES + ((size_t)b * NN + iidx) * 4);
    float ar = (rbx.z - rbx.x) * (rbx.w - rbx.y);

    if (rb == cb) {
        /* in-chunk 64x64 tile -> transposed diag tile */
        u64 m = 0;
#pragma unroll 8
        for (int j = 0; j < 64; j++) {
            float ix1 = fmaxf(rbx.x, sx1[j]);
            float iy1 = fmaxf(rbx.y, sy1[j]);
            float ix2 = fminf(rbx.z, sx2[j]);
            float iy2 = fminf(rbx.w, sy2[j]);
            float inter = fmaxf(ix2 - ix1, 0.0f) * fmaxf(iy2 - iy1, 0.0f);
            float uni = ar + sar[j] - inter;
            if (inter > 0.5f * fmaxf(uni, 1e-9f)) m |= 1ull << j;
        }
        m &= ~(1ull << t);
        srow[t] = m;
        __syncthreads();
        u64 ct = 0;
#pragma unroll 8
        for (int j = 0; j < 64; j++)
            ct |= ((srow[j] >> t) & 1ull) << j;
        g_diagT[b][rb][t] = ct;   /* ct bit j: in-chunk row j suppresses box t */
    } else {
        /* rows strictly earlier than cols: sparse append */
#pragma unroll 4
        for (int j = 0; j < 64; j++) {
            float ix1 = fmaxf(rbx.x, sx1[j]);
            float iy1 = fmaxf(rbx.y, sy1[j]);
            float ix2 = fminf(rbx.z, sx2[j]);
            float iy2 = fminf(rbx.w, sy2[j]);
            float inter = fmaxf(ix2 - ix1, 0.0f) * fmaxf(iy2 - iy1, 0.0f);
            float uni = ar + sar[j] - inter;
            if (inter > 0.5f * fmaxf(uni, 1e-9f)) {
                int col = cb * 64 + j;
                int pos = atomicAdd(&g_cnt[b][col], 1);
                if (pos < KCAP) g_list[b][col][pos] = (u32)i;
            }
        }
    }
}

/* ------------------------------------------------------------------ */
/* Kernel 4: greedy gather via sparse lists. Warp 0 runs all 128       */
/* phases with NO barriers; other warps preload smem + final scatter.  */
__global__ __launch_bounds__(1024, 1)
void gather_kernel(float* __restrict__ out)
{
    extern __shared__ u64 sm[];
    u64* colTall = sm;                 /* NW*64 u64 (64 KB) */
    u64* keepw   = colTall + NW * 64;  /* NW */
    u64* vwall   = keepw + NW;         /* NW */

    int b = blockIdx.x;
    int t = threadIdx.x;
    int lane = t & 31;
    int wrp  = t >> 5;

    for (int i = t; i < NW * 64; i += 1024)
        colTall[i] = g_diagT[b][0][i];

    /* validity bits in sorted order */
    for (int p = 0; p < NN; p += 1024) {
        int i = p + t;
        u32 si = g_sorted[b][i];
        int v = g_valid[b][si];
        u32 bal = __ballot_sync(0xffffffffu, v != 0);
        if (lane == 0) {
            ((u32*)vwall)[i >> 5] = bal;
        }
    }
    __syncthreads();

    if (wrp == 0) {
        u64 blo = (1ull << lane) - 1;
        u64 bhi = (1ull << (lane + 32)) - 1;

        /* prefetch counts for chunk 0 */
        int cnt0 = g_cnt[b][lane];
        int cnt1 = g_cnt[b][lane + 32];

        for (int c = 0; c < NW; c++) {
            int i0 = c * 64 + lane;
            int i1 = i0 + 32;

            /* external suppression: any kept suppressor (earlier chunks) */
            bool s0 = false, s1 = false;
            int n0 = min(cnt0, KCAP);
            for (int q = 0; q < n0; q++) {
                u32 j = g_list[b][i0][q];
                s0 |= ((keepw[j >> 6] >> (j & 63)) & 1ull) != 0;
            }
            int n1 = min(cnt1, KCAP);
            for (int q = 0; q < n1; q++) {
                u32 j = g_list[b][i1][q];
                s1 |= ((keepw[j >> 6] >> (j & 63)) & 1ull) != 0;
            }

            /* prefetch next chunk's counts */
            if (c + 1 < NW) {
                cnt0 = g_cnt[b][i0 + 64];
                cnt1 = g_cnt[b][i1 + 64];
            }

            u64 ext = (u64)__ballot_sync(0xffffffffu, s0)
                    | ((u64)__ballot_sync(0xffffffffu, s1) << 32);
            u64 veff = vwall[c] & ~ext;

            /* in-chunk ballot fixed point */
            u64 ct_lo = colTall[c * 64 + lane];
            u64 ct_hi = colTall[c * 64 + 32 + lane];
            bool v0 = (veff >> lane) & 1;
            bool v1 = (veff >> (lane + 32)) & 1;

            u64 k = veff;
            for (int it = 0; it < 70; it++) {
                bool c0 = v0 && ((ct_lo & k & blo) == 0);
                bool c1 = v1 && ((ct_hi & k & bhi) == 0);
                u32 lo = __ballot_sync(0xffffffffu, c0);
                u32 hi = __ballot_sync(0xffffffffu, c1);
                u64 kn = (u64)lo | ((u64)hi << 32);
                if (kn == k) break;
                k = kn;
            }

            if (lane == 0) keepw[c] = k;
            __syncwarp();
        }
    }
    __syncthreads();

    /* scatter keep back to original order */
    for (int i = t; i < NN; i += 1024) {
        u32 si = g_sorted[b][i];
        float kv = (float)((keepw[i >> 6] >> (i & 63)) & 1ull);
        out[OFF_KEEP + b * NN + si] = kv;
    }
}

/* ------------------------------------------------------------------ */
extern "C" void kernel_launch(void* const* d_in, const int* in_sizes, int n_in,
                              void* d_out, int out_size)
{
    (void)in_sizes; (void)n_in; (void)out_size;
    const float* logits  = (const float*)d_in[0];
    const float* deltas  = (const float*)d_in[1];
    const float* anchors = (const float*)d_in[2];
    float* out = (float*)d_out;

    cudaFuncSetAttribute(sort_kernel,
                         cudaFuncAttributeMaxDynamicSharedMemorySize,
                         NN * (int)sizeof(u64));
    int gsmem = (NW * 64 + 2 * NW) * (int)sizeof(u64) + 256;
    cudaFuncSetAttribute(gather_kernel,
                         cudaFuncAttributeMaxDynamicSharedMemorySize, gsmem);

    prep_kernel<<<(BB * NN * 32 + 255) / 256, 256>>>(logits, deltas, anchors, out);
    sort_kernel<<<BB, 1024, NN * sizeof(u64)>>>();
    {
        dim3 grid(NW * (NW + 1) / 2, BB);
        pairs_kernel<<<grid, 64>>>(out);
    }
    gather_kernel<<<BB, 1024, gsmem>>>(out);
}

// round 5
// speedup vs baseline: 4.7594x; 4.7594x over previous
#include <cuda_runtime.h>
#include <cstdint>

#define BB 2
#define NN 8192
#define CC 80
#define KCAP 128
#define NMS_BLOCKS 16

typedef unsigned long long u64;
typedef unsigned int u32;
typedef unsigned char u8;

/* output layout (concatenated flat float32, tuple order) */
#define OFF_BOXES 0
#define OFF_MS    (BB*NN*4)
#define OFF_LB    (OFF_MS + BB*NN)
#define OFF_KEEP  (OFF_LB + BB*NN)
#define OFF_ALL   (OFF_KEEP + BB*NN)

/* static device scratch (no allocation allowed) */
__device__ u64 g_keys[BB][NN];        /* packed priority: (~score_bits, idx) */
__device__ u8  g_validb[BB][NN];
__device__ u8  g_keep[BB][NN];
__device__ int g_cnt[BB][NN];         /* suppressor count per box */
__device__ u32 g_list[BB][NN][KCAP];  /* suppressor index lists */
__device__ int g_changed[72];
__device__ u32 g_bar;

/* ------------------------------------------------------------------ */
/* Kernel 0: zero counters / flags / barrier (runs every replay)       */
__global__ void init_kernel()
{
    int idx = blockIdx.x * blockDim.x + threadIdx.x;
    if (idx < BB * NN) ((int*)g_cnt)[idx] = 0;
    if (idx < 72) g_changed[idx] = 0;
    if (idx == 0) g_bar = 0;
}

/* ------------------------------------------------------------------ */
/* Kernel 1: sigmoid / max / argmax / box decode / valid / keys        */
__global__ void prep_kernel(const float* __restrict__ logits,
                            const float* __restrict__ deltas,
                            const float* __restrict__ anchors,
                            float* __restrict__ out)
{
    int wid  = (blockIdx.x * blockDim.x + threadIdx.x) >> 5;
    int lane = threadIdx.x & 31;
    if (wid >= BB * NN) return;
    int b = wid / NN, n = wid % NN;

    const float* lg = logits + (size_t)wid * CC;
    float* as_out   = out + OFF_ALL + (size_t)wid * CC;

    float v0 = lg[lane];
    float v1 = lg[lane + 32];
    float v2 = (lane < 16) ? lg[lane + 64] : -INFINITY;

    as_out[lane]      = 1.0f / (1.0f + expf(-v0));
    as_out[lane + 32] = 1.0f / (1.0f + expf(-v1));
    if (lane < 16) as_out[lane + 64] = 1.0f / (1.0f + expf(-v2));

    float mv = v0; int mi = lane;
    if (v1 > mv) { mv = v1; mi = lane + 32; }
    if (v2 > mv) { mv = v2; mi = lane + 64; }

    for (int off = 16; off; off >>= 1) {
        float ov = __shfl_down_sync(0xffffffffu, mv, off);
        int   oi = __shfl_down_sync(0xffffffffu, mi, off);
        if (ov > mv || (ov == mv && oi < mi)) { mv = ov; mi = oi; }
    }

    if (lane == 0) {
        float ms = 1.0f / (1.0f + expf(-mv));
        out[OFF_MS + wid] = ms;
        out[OFF_LB + wid] = (float)mi;

        const float* dl = deltas  + (size_t)wid * 4;
        const float* an = anchors + (size_t)n * 4;
        float a0 = an[0], a1 = an[1], a2 = an[2], a3 = an[3];
        float aw = a2 - a0, ah = a3 - a1;
        float acx = a0 + 0.5f * aw, acy = a1 + 0.5f * ah;
        float dx = dl[0], dy = dl[1];
        float dw = fminf(dl[2], 4.0f), dh = fminf(dl[3], 4.0f);
        float pcx = dx * aw + acx, pcy = dy * ah + acy;
        float pw = expf(dw) * aw, ph = expf(dh) * ah;
        float x1 = fminf(fmaxf(pcx - 0.5f * pw, 0.0f), 1.0f);
        float y1 = fminf(fmaxf(pcy - 0.5f * ph, 0.0f), 1.0f);
        float x2 = fminf(fmaxf(pcx + 0.5f * pw, 0.0f), 1.0f);
        float y2 = fminf(fmaxf(pcy + 0.5f * ph, 0.0f), 1.0f);

        float* bo = out + OFF_BOXES + (size_t)wid * 4;
        bo[0] = x1; bo[1] = y1; bo[2] = x2; bo[3] = y2;

        float w = x2 - x1, h = y2 - y1;
        u8 valid = (ms > 0.5f) && (w > 0.01f) && (h > 0.01f) &&
                   (w < 0.99f) && (h < 0.99f);
        g_validb[b][n] = valid;
        g_keep[b][n]   = valid;          /* k0 = valid (upper bound)  */

        u32 ksb = ~__float_as_uint(ms);  /* smaller key = higher prio */
        g_keys[b][n] = ((u64)ksb << 32) | (u32)n;
    }
}

/* ------------------------------------------------------------------ */
/* Kernel 2: sparse suppressor pairs, ORIGINAL order, triangular tiles */
/* For each pair with IoU > thr: smaller key suppresses larger key.    */
__global__ void pairs_kernel(const float* __restrict__ out)
{
    int b = blockIdx.y;
    int L = blockIdx.x;
    int cb = (int)((sqrtf(8.0f * (float)L + 1.0f) - 1.0f) * 0.5f);
    while ((cb + 1) * (cb + 2) / 2 <= L) cb++;
    while (cb * (cb + 1) / 2 > L) cb--;
    int rb = L - cb * (cb + 1) / 2;     /* rb <= cb */

    int t = threadIdx.x;  /* 64 threads, one per row box */

    __shared__ float sx1[64], sy1[64], sx2[64], sy2[64], sar[64];
    __shared__ u64 skey[64];

    int cj = cb * 64 + t;
    float4 cbx = *(const float4*)(out + OFF_BOXES + ((size_t)b * NN + cj) * 4);
    sx1[t] = cbx.x; sy1[t] = cbx.y; sx2[t] = cbx.z; sy2[t] = cbx.w;
    sar[t] = (cbx.z - cbx.x) * (cbx.w - cbx.y);
    skey[t] = g_keys[b][cj];
    __syncthreads();

    int i = rb * 64 + t;
    float4 rbx = *(const float4*)(out + OFF_BOXES + ((size_t)b * NN + i) * 4);
    float ar = (rbx.z - rbx.x) * (rbx.w - rbx.y);
    u64 kr = g_keys[b][i];

    int jstart = (rb == cb) ? (t + 1) : 0;   /* diagonal: each pair once */
    for (int j = jstart; j < 64; j++) {
        float ix1 = fmaxf(rbx.x, sx1[j]);
        float iy1 = fmaxf(rbx.y, sy1[j]);
        float ix2 = fminf(rbx.z, sx2[j]);
        float iy2 = fminf(rbx.w, sy2[j]);
        float inter = fmaxf(ix2 - ix1, 0.0f) * fmaxf(iy2 - iy1, 0.0f);
        float uni = ar + sar[j] - inter;
        if (inter > 0.5f * fmaxf(uni, 1e-9f)) {
            int ci = cb * 64 + j;
            int victim, supp;
            if (skey[j] < kr) { victim = i;  supp = ci; }
            else              { victim = ci; supp = i;  }
            int pos = atomicAdd(&g_cnt[b][victim], 1);
            if (pos < KCAP) g_list[b][victim][pos] = (u32)supp;
        }
    }
}

/* ------------------------------------------------------------------ */
/* Kernel 3: persistent parallel greedy-NMS fixed point.               */
/* 16 blocks x 1024 threads = one thread per box; async Jacobi sweeps  */
/* with software grid barrier; exact convergence check per sweep.      */
__global__ __launch_bounds__(1024, 2)
void nms_kernel(float* __restrict__ out)
{
    int t = blockIdx.x * 1024 + threadIdx.x;   /* 0 .. 16383 */
    int b = t >> 13;
    int i = t & (NN - 1);

    u8 valid = g_validb[b][i];
    int cnt = min(g_cnt[b][i], KCAP);
    const u32* lst = g_list[b][i];

    __shared__ int s_stop;
    u32 bar_target = 0;

    for (int sw = 0; sw < 64; sw++) {
        bool s = false;
        int q = 0;
        for (; q + 4 <= cnt; q += 4) {
            u32 j0 = lst[q], j1 = lst[q + 1], j2 = lst[q + 2], j3 = lst[q + 3];
            s = s | (g_keep[b][j0] | g_keep[b][j1] |
                     g_keep[b][j2] | g_keep[b][j3]);
        }
        for (; q < cnt; q++) s = s | g_keep[b][lst[q]];

        u8 nk = (u8)(valid && !s);
        bool ch = (nk != g_keep[b][i]);
        g_keep[b][i] = nk;

        u32 w = __ballot_sync(0xffffffffu, ch);
        if ((threadIdx.x & 31) == 0 && w) atomicExch(&g_changed[sw], 1);
        __threadfence();

        /* grid barrier */
        __syncthreads();
        bar_target += NMS_BLOCKS;
        if (threadIdx.x == 0) {
            atomicAdd(&g_bar, 1u);
            while (atomicAdd(&g_bar, 0u) < bar_target) { }
            s_stop = (atomicAdd(&g_changed[sw], 0) == 0);
        }
        __syncthreads();
        if (s_stop) break;
    }

    out[OFF_KEEP + b * NN + i] = (float)g_keep[b][i];
}

/* ------------------------------------------------------------------ */
extern "C" void kernel_launch(void* const* d_in, const int* in_sizes, int n_in,
                              void* d_out, int out_size)
{
    (void)in_sizes; (void)n_in; (void)out_size;
    const float* logits  = (const float*)d_in[0];
    const float* deltas  = (const float*)d_in[1];
    const float* anchors = (const float*)d_in[2];
    float* out = (float*)d_out;

    init_kernel<<<(BB * NN + 255) / 256, 256>>>();
    prep_kernel<<<(BB * NN * 32 + 255) / 256, 256>>>(logits, deltas, anchors, out);
    {
        int ntiles = (NN / 64) * (NN / 64 + 1) / 2;   /* 8256 */
        dim3 grid(ntiles, BB);
        pairs_kernel<<<grid, 64>>>(out);
    }
    nms_kernel<<<NMS_BLOCKS, 1024>>>(out);
}